// round 14
// baseline (speedup 1.0000x reference)
#include <cuda_runtime.h>
#include <cstdint>

#define EMB   512
#define BQ    8
#define ROW   (2*EMB)
#define GAMMA_F 12.0f

// Rotated query embeddings (computed once per launch by prologue kernel).
__device__ float g_qre[BQ * EMB];
__device__ float g_qim[BQ * EMB];

__device__ __forceinline__ float fsqrt_fast(float x) {
    float y;
    asm("sqrt.approx.f32 %0, %1;" : "=f"(y) : "f"(x));
    return y;
}

// ---------------------------------------------------------------------------
// Kernel A: compute rotated query h*r for the 8 queries (8 x 512 complex).
// grid = BQ blocks, block = EMB threads. Tiny; cost is negligible.
// ---------------------------------------------------------------------------
__global__ void rotate_query_kernel(const int* __restrict__ all_h,
                                    const int* __restrict__ all_r,
                                    const float* __restrict__ eemb,
                                    const float* __restrict__ remb) {
    const int b = blockIdx.x;
    const int j = threadIdx.x;
    const int h = all_h[b];
    const int r = all_r[b];

    const float re_h = eemb[(size_t)h * ROW + j];
    const float im_h = eemb[(size_t)h * ROW + EMB + j];

    // phase = remb / (PHASE_RANGE / pi),  PHASE_RANGE = (GAMMA+2)/EMB = 14/512
    const float scale = (float)(3.141592653589793 * (double)EMB / 14.0);
    const float phase = remb[(size_t)r * EMB + j] * scale;

    float s, c;
    sincosf(phase, &s, &c);

    g_qre[b * EMB + j] = re_h * c - im_h * s;
    g_qim[b * EMB + j] = re_h * s + im_h * c;
}

// ---------------------------------------------------------------------------
// Kernel B: score all N entities against all 8 rotated queries.
// Block = 256 threads (8 warps). Each warp processes 2 entities per iteration
// (query smem loads amortized over both). Lane l owns dims {4l..4l+3} + 128k.
// ---------------------------------------------------------------------------
__global__ void __launch_bounds__(256, 2)
rotate_score_kernel(const float* __restrict__ eemb,
                    float* __restrict__ out,
                    int N) {
    __shared__ float sqre[BQ * EMB];
    __shared__ float sqim[BQ * EMB];

    // Cooperative load of rotated queries into smem (32 KB total).
    {
        const float4* gre = (const float4*)g_qre;
        const float4* gim = (const float4*)g_qim;
        float4* sre = (float4*)sqre;
        float4* sim = (float4*)sqim;
        for (int i = threadIdx.x; i < BQ * EMB / 4; i += 256) {
            sre[i] = gre[i];
            sim[i] = gim[i];
        }
    }
    __syncthreads();

    const int lane = threadIdx.x & 31;
    const int warp = threadIdx.x >> 5;
    const int wgid = blockIdx.x * 8 + warp;
    const int nW   = gridDim.x * 8;

    const float4* q_re4 = (const float4*)sqre;
    const float4* q_im4 = (const float4*)sqim;

    for (int e0 = wgid * 2; e0 < N; e0 += nW * 2) {
        const int  e1   = e0 + 1;
        const bool has1 = (e1 < N);

        const float4* r0 = (const float4*)(eemb + (size_t)e0 * ROW);
        const float4* r1 = has1 ? (const float4*)(eemb + (size_t)e1 * ROW) : r0;

        // Entity data register-resident across all 8 queries.
        float4 xr0[4], xi0[4], xr1[4], xi1[4];
#pragma unroll
        for (int k = 0; k < 4; k++) {
            xr0[k] = r0[k * 32 + lane];
            xi0[k] = r0[128 + k * 32 + lane];
            xr1[k] = r1[k * 32 + lane];
            xi1[k] = r1[128 + k * 32 + lane];
        }

#pragma unroll 2
        for (int b = 0; b < BQ; b++) {
            float acc0 = 0.0f, acc1 = 0.0f;
#pragma unroll
            for (int k = 0; k < 4; k++) {
                float4 qr = q_re4[b * 128 + k * 32 + lane];
                float4 qi = q_im4[b * 128 + k * 32 + lane];
                const float* qrv = (const float*)&qr;
                const float* qiv = (const float*)&qi;
                const float* x0r = (const float*)&xr0[k];
                const float* x0i = (const float*)&xi0[k];
                const float* x1r = (const float*)&xr1[k];
                const float* x1i = (const float*)&xi1[k];
#pragma unroll
                for (int c = 0; c < 4; c++) {
                    float dr0 = qrv[c] - x0r[c];
                    float di0 = qiv[c] - x0i[c];
                    acc0 += fsqrt_fast(dr0 * dr0 + di0 * di0);
                    float dr1 = qrv[c] - x1r[c];
                    float di1 = qiv[c] - x1i[c];
                    acc1 += fsqrt_fast(dr1 * dr1 + di1 * di1);
                }
            }
            // Warp-wide sum over the 512 dims (16 per lane).
#pragma unroll
            for (int off = 16; off; off >>= 1) {
                acc0 += __shfl_xor_sync(0xffffffffu, acc0, off);
                acc1 += __shfl_xor_sync(0xffffffffu, acc1, off);
            }
            if (lane == 0) {
                out[(size_t)b * N + e0] = GAMMA_F - acc0;
                if (has1) out[(size_t)b * N + e1] = GAMMA_F - acc1;
            }
        }
    }
}

// ---------------------------------------------------------------------------
// kernel_launch — graph-capturable: two kernel launches on the default stream,
// no allocation, no sync. Scratch lives in __device__ globals.
// ---------------------------------------------------------------------------
extern "C" void kernel_launch(void* const* d_in, const int* in_sizes, int n_in,
                              void* d_out, int out_size) {
    const int*   all_h = (const int*)d_in[0];
    const int*   all_r = (const int*)d_in[1];
    const float* eemb  = (const float*)d_in[2];
    const float* remb  = (const float*)d_in[3];
    float*       out   = (float*)d_out;

    const int N = in_sizes[2] / ROW;   // 30000

    rotate_query_kernel<<<BQ, EMB>>>(all_h, all_r, eemb, remb);
    rotate_score_kernel<<<296, 256>>>(eemb, out, N);
}

// round 15
// speedup vs baseline: 1.0006x; 1.0006x over previous
#include <cuda_runtime.h>
#include <cstdint>

#define EMB   512
#define BQ    8
#define ROW   (2*EMB)
#define GAMMA_F 12.0f

// Rotated query embeddings (computed once per launch by prologue kernel).
__device__ float g_qre[BQ * EMB];
__device__ float g_qim[BQ * EMB];

__device__ __forceinline__ float fsqrt_fast(float x) {
    float y;
    asm("sqrt.approx.f32 %0, %1;" : "=f"(y) : "f"(x));
    return y;
}

// ---------------------------------------------------------------------------
// Kernel A: compute rotated query h*r for the 8 queries (8 x 512 complex).
// grid = BQ blocks, block = EMB threads. Tiny; cost is negligible.
// ---------------------------------------------------------------------------
__global__ void rotate_query_kernel(const int* __restrict__ all_h,
                                    const int* __restrict__ all_r,
                                    const float* __restrict__ eemb,
                                    const float* __restrict__ remb) {
    const int b = blockIdx.x;
    const int j = threadIdx.x;
    const int h = all_h[b];
    const int r = all_r[b];

    const float re_h = eemb[(size_t)h * ROW + j];
    const float im_h = eemb[(size_t)h * ROW + EMB + j];

    // phase = remb / (PHASE_RANGE / pi),  PHASE_RANGE = (GAMMA+2)/EMB = 14/512
    const float scale = (float)(3.141592653589793 * (double)EMB / 14.0);
    const float phase = remb[(size_t)r * EMB + j] * scale;

    float s, c;
    sincosf(phase, &s, &c);

    g_qre[b * EMB + j] = re_h * c - im_h * s;
    g_qim[b * EMB + j] = re_h * s + im_h * c;
}

// ---------------------------------------------------------------------------
// Kernel B: score all N entities against all 8 rotated queries.
// Block = 256 threads (8 warps). Each warp processes 2 entities per iteration
// (query smem loads amortized over both). Lane l owns dims {4l..4l+3} + 128k.
// ---------------------------------------------------------------------------
__global__ void __launch_bounds__(256, 2)
rotate_score_kernel(const float* __restrict__ eemb,
                    float* __restrict__ out,
                    int N) {
    __shared__ float sqre[BQ * EMB];
    __shared__ float sqim[BQ * EMB];

    // Cooperative load of rotated queries into smem (32 KB total).
    {
        const float4* gre = (const float4*)g_qre;
        const float4* gim = (const float4*)g_qim;
        float4* sre = (float4*)sqre;
        float4* sim = (float4*)sqim;
        for (int i = threadIdx.x; i < BQ * EMB / 4; i += 256) {
            sre[i] = gre[i];
            sim[i] = gim[i];
        }
    }
    __syncthreads();

    const int lane = threadIdx.x & 31;
    const int warp = threadIdx.x >> 5;
    const int wgid = blockIdx.x * 8 + warp;
    const int nW   = gridDim.x * 8;

    const float4* q_re4 = (const float4*)sqre;
    const float4* q_im4 = (const float4*)sqim;

    for (int e0 = wgid * 2; e0 < N; e0 += nW * 2) {
        const int  e1   = e0 + 1;
        const bool has1 = (e1 < N);

        const float4* r0 = (const float4*)(eemb + (size_t)e0 * ROW);
        const float4* r1 = has1 ? (const float4*)(eemb + (size_t)e1 * ROW) : r0;

        // Entity data register-resident across all 8 queries.
        float4 xr0[4], xi0[4], xr1[4], xi1[4];
#pragma unroll
        for (int k = 0; k < 4; k++) {
            xr0[k] = r0[k * 32 + lane];
            xi0[k] = r0[128 + k * 32 + lane];
            xr1[k] = r1[k * 32 + lane];
            xi1[k] = r1[128 + k * 32 + lane];
        }

#pragma unroll 2
        for (int b = 0; b < BQ; b++) {
            float acc0 = 0.0f, acc1 = 0.0f;
#pragma unroll
            for (int k = 0; k < 4; k++) {
                float4 qr = q_re4[b * 128 + k * 32 + lane];
                float4 qi = q_im4[b * 128 + k * 32 + lane];
                const float* qrv = (const float*)&qr;
                const float* qiv = (const float*)&qi;
                const float* x0r = (const float*)&xr0[k];
                const float* x0i = (const float*)&xi0[k];
                const float* x1r = (const float*)&xr1[k];
                const float* x1i = (const float*)&xi1[k];
#pragma unroll
                for (int c = 0; c < 4; c++) {
                    float dr0 = qrv[c] - x0r[c];
                    float di0 = qiv[c] - x0i[c];
                    acc0 += fsqrt_fast(dr0 * dr0 + di0 * di0);
                    float dr1 = qrv[c] - x1r[c];
                    float di1 = qiv[c] - x1i[c];
                    acc1 += fsqrt_fast(dr1 * dr1 + di1 * di1);
                }
            }
            // Warp-wide sum over the 512 dims (16 per lane).
#pragma unroll
            for (int off = 16; off; off >>= 1) {
                acc0 += __shfl_xor_sync(0xffffffffu, acc0, off);
                acc1 += __shfl_xor_sync(0xffffffffu, acc1, off);
            }
            if (lane == 0) {
                out[(size_t)b * N + e0] = GAMMA_F - acc0;
                if (has1) out[(size_t)b * N + e1] = GAMMA_F - acc1;
            }
        }
    }
}

// ---------------------------------------------------------------------------
// kernel_launch — graph-capturable: two kernel launches on the default stream,
// no allocation, no sync. Scratch lives in __device__ globals.
// ---------------------------------------------------------------------------
extern "C" void kernel_launch(void* const* d_in, const int* in_sizes, int n_in,
                              void* d_out, int out_size) {
    const int*   all_h = (const int*)d_in[0];
    const int*   all_r = (const int*)d_in[1];
    const float* eemb  = (const float*)d_in[2];
    const float* remb  = (const float*)d_in[3];
    float*       out   = (float*)d_out;

    const int N = in_sizes[2] / ROW;   // 30000

    rotate_query_kernel<<<BQ, EMB>>>(all_h, all_r, eemb, remb);
    rotate_score_kernel<<<296, 256>>>(eemb, out, N);
}

// round 16
// speedup vs baseline: 1.0653x; 1.0647x over previous
#include <cuda_runtime.h>
#include <cstdint>

#define EMB   512
#define BQ    8
#define ROW   (2*EMB)
#define GAMMA_F 12.0f

typedef unsigned long long u64;

// Rotated query embeddings (computed once per launch by prologue kernel).
__device__ float g_qre[BQ * EMB];
__device__ float g_qim[BQ * EMB];

// ---- Blackwell packed f32x2 ops (dual-rate FFMA2; PTX-only, per SASS_QUICKREF) ----
__device__ __forceinline__ u64 fma2(u64 a, u64 b, u64 c) {
    u64 r; asm("fma.rn.f32x2 %0, %1, %2, %3;" : "=l"(r) : "l"(a), "l"(b), "l"(c)); return r;
}
__device__ __forceinline__ u64 mul2(u64 a, u64 b) {
    u64 r; asm("mul.rn.f32x2 %0, %1, %2;" : "=l"(r) : "l"(a), "l"(b)); return r;
}
__device__ __forceinline__ void unpack2(u64 v, float& lo, float& hi) {
    asm("mov.b64 {%0, %1}, %2;" : "=f"(lo), "=f"(hi) : "l"(v));
}
__device__ __forceinline__ float fsqrt_fast(float x) {
    float y; asm("sqrt.approx.f32 %0, %1;" : "=f"(y) : "f"(x)); return y;
}

// ---------------------------------------------------------------------------
// Kernel A: rotated query h*r for the 8 queries (8 x 512 complex). Negligible.
// ---------------------------------------------------------------------------
__global__ void rotate_query_kernel(const int* __restrict__ all_h,
                                    const int* __restrict__ all_r,
                                    const float* __restrict__ eemb,
                                    const float* __restrict__ remb) {
    const int b = blockIdx.x;
    const int j = threadIdx.x;
    const int h = all_h[b];
    const int r = all_r[b];

    const float re_h = eemb[(size_t)h * ROW + j];
    const float im_h = eemb[(size_t)h * ROW + EMB + j];

    // phase = remb / (PHASE_RANGE / pi),  PHASE_RANGE = (GAMMA+2)/EMB = 14/512
    const float scale = (float)(3.141592653589793 * (double)EMB / 14.0);
    const float phase = remb[(size_t)r * EMB + j] * scale;

    float s, c;
    sincosf(phase, &s, &c);

    g_qre[b * EMB + j] = re_h * c - im_h * s;
    g_qim[b * EMB + j] = re_h * s + im_h * c;
}

// ---------------------------------------------------------------------------
// Kernel B: score all N entities against all 8 rotated queries.
// Warp-per-entity-pair; lane owns 16 dims (4 x float4 groups). All difference
// /square/accumulate math packed 2-wide via f32x2 — FMA-pipe instr count
// drops 40% vs scalar; MUFU (1 sqrt/dim) becomes the binding pipe.
// ---------------------------------------------------------------------------
__global__ void __launch_bounds__(256, 2)
rotate_score_kernel(const float* __restrict__ eemb,
                    float* __restrict__ out,
                    int N) {
    __shared__ float sqre[BQ * EMB];
    __shared__ float sqim[BQ * EMB];

    // Cooperative load of rotated queries into smem (32 KB total).
    {
        const float4* gre = (const float4*)g_qre;
        const float4* gim = (const float4*)g_qim;
        float4* sre = (float4*)sqre;
        float4* sim = (float4*)sqim;
        for (int i = threadIdx.x; i < BQ * EMB / 4; i += 256) {
            sre[i] = gre[i];
            sim[i] = gim[i];
        }
    }
    __syncthreads();

    const int lane = threadIdx.x & 31;
    const int warp = threadIdx.x >> 5;
    const int wgid = blockIdx.x * 8 + warp;
    const int nW   = gridDim.x * 8;

    const ulonglong2* q_re2 = (const ulonglong2*)sqre;
    const ulonglong2* q_im2 = (const ulonglong2*)sqim;

    const u64 M1 = 0xBF800000BF800000ULL;   // packed (-1.0f, -1.0f)

    for (int e0 = wgid * 2; e0 < N; e0 += nW * 2) {
        const int  e1   = e0 + 1;
        const bool has1 = (e1 < N);

        const ulonglong2* r0 = (const ulonglong2*)(eemb + (size_t)e0 * ROW);
        const ulonglong2* r1 = has1 ? (const ulonglong2*)(eemb + (size_t)e1 * ROW) : r0;

        // Entity data register-resident across all 8 queries (as f32x2 pairs).
        u64 xr0[8], xi0[8], xr1[8], xi1[8];
#pragma unroll
        for (int k = 0; k < 4; k++) {
            ulonglong2 a = r0[k * 32 + lane];        xr0[2*k] = a.x; xr0[2*k+1] = a.y;
            ulonglong2 b = r0[128 + k * 32 + lane];  xi0[2*k] = b.x; xi0[2*k+1] = b.y;
            ulonglong2 c = r1[k * 32 + lane];        xr1[2*k] = c.x; xr1[2*k+1] = c.y;
            ulonglong2 d = r1[128 + k * 32 + lane];  xi1[2*k] = d.x; xi1[2*k+1] = d.y;
        }

#pragma unroll 2
        for (int b = 0; b < BQ; b++) {
            float a0 = 0.f, b0 = 0.f, a1 = 0.f, b1 = 0.f;
#pragma unroll
            for (int k = 0; k < 4; k++) {
                ulonglong2 qr = q_re2[b * 128 + k * 32 + lane];
                ulonglong2 qi = q_im2[b * 128 + k * 32 + lane];
#pragma unroll
                for (int p = 0; p < 2; p++) {
                    const u64 qrp = p ? qr.y : qr.x;
                    const u64 qip = p ? qi.y : qi.x;
                    float lo, hi;
                    // entity 0: d = q - x via packed fma(x, -1, q)
                    u64 dr = fma2(xr0[2*k + p], M1, qrp);
                    u64 di = fma2(xi0[2*k + p], M1, qip);
                    u64 t  = mul2(dr, dr);
                    t      = fma2(di, di, t);
                    unpack2(t, lo, hi);
                    a0 += fsqrt_fast(lo);
                    b0 += fsqrt_fast(hi);
                    // entity 1
                    dr = fma2(xr1[2*k + p], M1, qrp);
                    di = fma2(xi1[2*k + p], M1, qip);
                    t  = mul2(dr, dr);
                    t  = fma2(di, di, t);
                    unpack2(t, lo, hi);
                    a1 += fsqrt_fast(lo);
                    b1 += fsqrt_fast(hi);
                }
            }
            float acc0 = a0 + b0;
            float acc1 = a1 + b1;
            // Warp-wide sum over the 512 dims (16 per lane).
#pragma unroll
            for (int off = 16; off; off >>= 1) {
                acc0 += __shfl_xor_sync(0xffffffffu, acc0, off);
                acc1 += __shfl_xor_sync(0xffffffffu, acc1, off);
            }
            if (lane == 0) {
                out[(size_t)b * N + e0] = GAMMA_F - acc0;
                if (has1) out[(size_t)b * N + e1] = GAMMA_F - acc1;
            }
        }
    }
}

// ---------------------------------------------------------------------------
// kernel_launch — graph-capturable: two kernel launches, no alloc, no sync.
// ---------------------------------------------------------------------------
extern "C" void kernel_launch(void* const* d_in, const int* in_sizes, int n_in,
                              void* d_out, int out_size) {
    const int*   all_h = (const int*)d_in[0];
    const int*   all_r = (const int*)d_in[1];
    const float* eemb  = (const float*)d_in[2];
    const float* remb  = (const float*)d_in[3];
    float*       out   = (float*)d_out;

    const int N = in_sizes[2] / ROW;   // 30000

    rotate_query_kernel<<<BQ, EMB>>>(all_h, all_r, eemb, remb);
    rotate_score_kernel<<<296, 256>>>(eemb, out, N);
}

// round 17
// speedup vs baseline: 1.0705x; 1.0050x over previous
#include <cuda_runtime.h>
#include <cstdint>

#define EMB   512
#define BQ    8
#define ROW   (2*EMB)
#define GAMMA_F 12.0f

typedef unsigned long long u64;

// Rotated query embeddings (computed once per launch by prologue kernel).
__device__ float g_qre[BQ * EMB];
__device__ float g_qim[BQ * EMB];

// ---- Blackwell packed f32x2 ops (dual-rate FFMA2; PTX-only, per SASS_QUICKREF) ----
__device__ __forceinline__ u64 fma2(u64 a, u64 b, u64 c) {
    u64 r; asm("fma.rn.f32x2 %0, %1, %2, %3;" : "=l"(r) : "l"(a), "l"(b), "l"(c)); return r;
}
__device__ __forceinline__ u64 mul2(u64 a, u64 b) {
    u64 r; asm("mul.rn.f32x2 %0, %1, %2;" : "=l"(r) : "l"(a), "l"(b)); return r;
}
__device__ __forceinline__ void unpack2(u64 v, float& lo, float& hi) {
    asm("mov.b64 {%0, %1}, %2;" : "=f"(lo), "=f"(hi) : "l"(v));
}
__device__ __forceinline__ float fsqrt_fast(float x) {
    float y; asm("sqrt.approx.f32 %0, %1;" : "=f"(y) : "f"(x)); return y;
}

// ---------------------------------------------------------------------------
// Kernel A: rotated query h*r for the 8 queries (8 x 512 complex). Negligible.
// ---------------------------------------------------------------------------
__global__ void rotate_query_kernel(const int* __restrict__ all_h,
                                    const int* __restrict__ all_r,
                                    const float* __restrict__ eemb,
                                    const float* __restrict__ remb) {
    const int b = blockIdx.x;
    const int j = threadIdx.x;
    const int h = all_h[b];
    const int r = all_r[b];

    const float re_h = eemb[(size_t)h * ROW + j];
    const float im_h = eemb[(size_t)h * ROW + EMB + j];

    // phase = remb / (PHASE_RANGE / pi),  PHASE_RANGE = (GAMMA+2)/EMB = 14/512
    const float scale = (float)(3.141592653589793 * (double)EMB / 14.0);
    const float phase = remb[(size_t)r * EMB + j] * scale;

    float s, c;
    sincosf(phase, &s, &c);

    g_qre[b * EMB + j] = re_h * c - im_h * s;
    g_qim[b * EMB + j] = re_h * s + im_h * c;
}

// ---------------------------------------------------------------------------
// Kernel B: score all N entities against all 8 rotated queries.
// Warp-per-entity-pair; lane owns 16 dims (4 x float4 groups). All difference
// /square/accumulate math packed 2-wide via f32x2 — FMA-pipe instr count
// drops 40% vs scalar; MUFU (1 sqrt/dim) becomes the binding pipe.
// ---------------------------------------------------------------------------
__global__ void __launch_bounds__(256, 2)
rotate_score_kernel(const float* __restrict__ eemb,
                    float* __restrict__ out,
                    int N) {
    __shared__ float sqre[BQ * EMB];
    __shared__ float sqim[BQ * EMB];

    // Cooperative load of rotated queries into smem (32 KB total).
    {
        const float4* gre = (const float4*)g_qre;
        const float4* gim = (const float4*)g_qim;
        float4* sre = (float4*)sqre;
        float4* sim = (float4*)sqim;
        for (int i = threadIdx.x; i < BQ * EMB / 4; i += 256) {
            sre[i] = gre[i];
            sim[i] = gim[i];
        }
    }
    __syncthreads();

    const int lane = threadIdx.x & 31;
    const int warp = threadIdx.x >> 5;
    const int wgid = blockIdx.x * 8 + warp;
    const int nW   = gridDim.x * 8;

    const ulonglong2* q_re2 = (const ulonglong2*)sqre;
    const ulonglong2* q_im2 = (const ulonglong2*)sqim;

    const u64 M1 = 0xBF800000BF800000ULL;   // packed (-1.0f, -1.0f)

    for (int e0 = wgid * 2; e0 < N; e0 += nW * 2) {
        const int  e1   = e0 + 1;
        const bool has1 = (e1 < N);

        const ulonglong2* r0 = (const ulonglong2*)(eemb + (size_t)e0 * ROW);
        const ulonglong2* r1 = has1 ? (const ulonglong2*)(eemb + (size_t)e1 * ROW) : r0;

        // Entity data register-resident across all 8 queries (as f32x2 pairs).
        u64 xr0[8], xi0[8], xr1[8], xi1[8];
#pragma unroll
        for (int k = 0; k < 4; k++) {
            ulonglong2 a = r0[k * 32 + lane];        xr0[2*k] = a.x; xr0[2*k+1] = a.y;
            ulonglong2 b = r0[128 + k * 32 + lane];  xi0[2*k] = b.x; xi0[2*k+1] = b.y;
            ulonglong2 c = r1[k * 32 + lane];        xr1[2*k] = c.x; xr1[2*k+1] = c.y;
            ulonglong2 d = r1[128 + k * 32 + lane];  xi1[2*k] = d.x; xi1[2*k+1] = d.y;
        }

#pragma unroll 2
        for (int b = 0; b < BQ; b++) {
            float a0 = 0.f, b0 = 0.f, a1 = 0.f, b1 = 0.f;
#pragma unroll
            for (int k = 0; k < 4; k++) {
                ulonglong2 qr = q_re2[b * 128 + k * 32 + lane];
                ulonglong2 qi = q_im2[b * 128 + k * 32 + lane];
#pragma unroll
                for (int p = 0; p < 2; p++) {
                    const u64 qrp = p ? qr.y : qr.x;
                    const u64 qip = p ? qi.y : qi.x;
                    float lo, hi;
                    // entity 0: d = q - x via packed fma(x, -1, q)
                    u64 dr = fma2(xr0[2*k + p], M1, qrp);
                    u64 di = fma2(xi0[2*k + p], M1, qip);
                    u64 t  = mul2(dr, dr);
                    t      = fma2(di, di, t);
                    unpack2(t, lo, hi);
                    a0 += fsqrt_fast(lo);
                    b0 += fsqrt_fast(hi);
                    // entity 1
                    dr = fma2(xr1[2*k + p], M1, qrp);
                    di = fma2(xi1[2*k + p], M1, qip);
                    t  = mul2(dr, dr);
                    t  = fma2(di, di, t);
                    unpack2(t, lo, hi);
                    a1 += fsqrt_fast(lo);
                    b1 += fsqrt_fast(hi);
                }
            }
            float acc0 = a0 + b0;
            float acc1 = a1 + b1;
            // Warp-wide sum over the 512 dims (16 per lane).
#pragma unroll
            for (int off = 16; off; off >>= 1) {
                acc0 += __shfl_xor_sync(0xffffffffu, acc0, off);
                acc1 += __shfl_xor_sync(0xffffffffu, acc1, off);
            }
            if (lane == 0) {
                out[(size_t)b * N + e0] = GAMMA_F - acc0;
                if (has1) out[(size_t)b * N + e1] = GAMMA_F - acc1;
            }
        }
    }
}

// ---------------------------------------------------------------------------
// kernel_launch — graph-capturable: two kernel launches, no alloc, no sync.
// ---------------------------------------------------------------------------
extern "C" void kernel_launch(void* const* d_in, const int* in_sizes, int n_in,
                              void* d_out, int out_size) {
    const int*   all_h = (const int*)d_in[0];
    const int*   all_r = (const int*)d_in[1];
    const float* eemb  = (const float*)d_in[2];
    const float* remb  = (const float*)d_in[3];
    float*       out   = (float*)d_out;

    const int N = in_sizes[2] / ROW;   // 30000

    rotate_query_kernel<<<BQ, EMB>>>(all_h, all_r, eemb, remb);
    rotate_score_kernel<<<296, 256>>>(eemb, out, N);
}